// round 3
// baseline (speedup 1.0000x reference)
#include <cuda_runtime.h>
#include <math.h>

#define BB 8
#define SN 512
#define SIDX 256
#define DF 768
#define NH 12
#define HD 64
#define PJ 256
#define HID 128
#define VOC 16384
#define KTOP 20

// ---------------- scratch (static device globals; no allocations) ------------
__device__ float g_emb[BB*SN*DF];
__device__ float g_q  [BB*SIDX*DF];
__device__ float g_kb [BB*SN*DF];
__device__ float g_vb [BB*SN*DF];
__device__ float g_s  [BB*NH*SIDX*SN];
__device__ float g_o  [BB*SIDX*DF];
__device__ float g_mha[BB*SIDX*DF];
__device__ float g_xp [BB*SN*PJ];
__device__ float g_x1 [BB*SN*768];
__device__ float g_h1 [BB*SN*HID];
__device__ float g_x2 [BB*SN*384];
__device__ float g_h2 [BB*SN*HID];
__device__ float g_e  [BB*SN*DF];
__device__ float g_sq [BB*SN];
__device__ float g_w  [BB*SN*SN];
__device__ unsigned char g_mk[BB*SN*SN];
__device__ float g_dsi[BB*SN];
__device__ float g_A  [BB*SN*SN];
__device__ float g_Xa [BB*SN*SN];
__device__ float g_Xb [BB*SN*SN];
__device__ float g_T  [BB*SN*SN];
__device__ float g_w1r[HID*768];
__device__ float g_w2r[HID*384];

// ---------------- generic batched GEMM (pipelined) ----------------------------
// C = epi( A(MxK) * op(B) ) ; BT=1: B is [N,K] (C=A*B^T), BT=0: B is [K,N]
// batch z: zb=z/zdiv, zr=z%zdiv; ptr += zb*s1 + zr*s2
// EPI: 0 scale  1 +bias  2 conv+bn+relu  3 gaussian-W  4 newton (2*X - acc)
struct GemmP {
    const float* A; const float* B; float* C;
    int N, K, lda, ldb, ldc, zdiv;
    long sA1, sA2, sB1, sB2, sC1, sC2, sP0;
    float scale;
    const float* p0; const float* p1; const float* p2;
};

#define LDSR 132   // padded smem row stride (floats); 132*4B = 33*16B (float4-aligned)

template<int EPI, int BT>
__global__ void __launch_bounds__(256, 2) gemm_k(GemmP p) {
    __shared__ float As[2][8 * LDSR];
    __shared__ float Bs[2][8 * LDSR];
    int z  = blockIdx.z;
    int zb = z / p.zdiv, zr = z % p.zdiv;
    const float* Ap = p.A + zb * p.sA1 + (long)zr * p.sA2;
    const float* Bp = p.B + zb * p.sB1 + (long)zr * p.sB2;
    float*       Cp = p.C + zb * p.sC1 + (long)zr * p.sC2;
    int bm = blockIdx.y * 128, bn = blockIdx.x * 128;
    int tid = threadIdx.x;
    int tx = tid & 15, ty = tid >> 4;

    // A/BT=1 loader coords: one float4 per thread, row r, k-quad kq
    int lr = tid >> 1, lkq = (tid & 1) * 4;
    // BT=0 loader coords
    int lkr = tid >> 5, lnc = (tid & 31) * 4;

    float acc[8][8];
#pragma unroll
    for (int i = 0; i < 8; i++)
#pragma unroll
        for (int j = 0; j < 8; j++) acc[i][j] = 0.f;

    int nIter = p.K >> 3;

    // ---- prologue: stage tile 0 ----
    float4 rA, rB;
    {
        rA = *(const float4*)(Ap + (long)(bm + lr) * p.lda + lkq);
        if (BT) {
            int n = bn + lr;
            rB = make_float4(0.f,0.f,0.f,0.f);
            if (n < p.N) rB = *(const float4*)(Bp + (long)n * p.ldb + lkq);
        } else {
            int n = bn + lnc;
            rB = make_float4(0.f,0.f,0.f,0.f);
            if (n < p.N) rB = *(const float4*)(Bp + (long)lkr * p.ldb + n);
        }
        float* as = As[0]; float* bs = Bs[0];
        as[(lkq+0)*LDSR + lr] = rA.x; as[(lkq+1)*LDSR + lr] = rA.y;
        as[(lkq+2)*LDSR + lr] = rA.z; as[(lkq+3)*LDSR + lr] = rA.w;
        if (BT) {
            bs[(lkq+0)*LDSR + lr] = rB.x; bs[(lkq+1)*LDSR + lr] = rB.y;
            bs[(lkq+2)*LDSR + lr] = rB.z; bs[(lkq+3)*LDSR + lr] = rB.w;
        } else {
            *(float4*)&bs[lkr*LDSR + lnc] = rB;
        }
    }
    __syncthreads();

    for (int it = 0; it < nIter; it++) {
        int cur = it & 1;
        bool has = (it + 1 < nIter);
        // ---- issue next tile's global loads early ----
        if (has) {
            int k0 = (it + 1) << 3;
            rA = *(const float4*)(Ap + (long)(bm + lr) * p.lda + k0 + lkq);
            if (BT) {
                int n = bn + lr;
                rB = make_float4(0.f,0.f,0.f,0.f);
                if (n < p.N) rB = *(const float4*)(Bp + (long)n * p.ldb + k0 + lkq);
            } else {
                int n = bn + lnc;
                rB = make_float4(0.f,0.f,0.f,0.f);
                if (n < p.N) rB = *(const float4*)(Bp + (long)(k0 + lkr) * p.ldb + n);
            }
        }
        // ---- compute current tile ----
        const float* as = As[cur]; const float* bs = Bs[cur];
#pragma unroll
        for (int kk = 0; kk < 8; kk++) {
            float4 a0 = *(const float4*)&as[kk*LDSR + ty*8];
            float4 a1 = *(const float4*)&as[kk*LDSR + ty*8 + 4];
            float4 b0 = *(const float4*)&bs[kk*LDSR + tx*8];
            float4 b1 = *(const float4*)&bs[kk*LDSR + tx*8 + 4];
            float av[8] = {a0.x,a0.y,a0.z,a0.w,a1.x,a1.y,a1.z,a1.w};
            float bv[8] = {b0.x,b0.y,b0.z,b0.w,b1.x,b1.y,b1.z,b1.w};
#pragma unroll
            for (int i = 0; i < 8; i++)
#pragma unroll
                for (int j = 0; j < 8; j++) acc[i][j] += av[i]*bv[j];
        }
        // ---- commit staged regs into the other buffer ----
        if (has) {
            int nxt = cur ^ 1;
            float* asw = As[nxt]; float* bsw = Bs[nxt];
            asw[(lkq+0)*LDSR + lr] = rA.x; asw[(lkq+1)*LDSR + lr] = rA.y;
            asw[(lkq+2)*LDSR + lr] = rA.z; asw[(lkq+3)*LDSR + lr] = rA.w;
            if (BT) {
                bsw[(lkq+0)*LDSR + lr] = rB.x; bsw[(lkq+1)*LDSR + lr] = rB.y;
                bsw[(lkq+2)*LDSR + lr] = rB.z; bsw[(lkq+3)*LDSR + lr] = rB.w;
            } else {
                *(float4*)&bsw[lkr*LDSR + lnc] = rB;
            }
        }
        __syncthreads();
    }

    const float* P0 = p.p0;
    if (EPI == 3 || EPI == 4) P0 = p.p0 + zb * p.sP0;
#pragma unroll
    for (int i = 0; i < 8; i++) {
        int m = bm + ty*8 + i;
#pragma unroll
        for (int j = 0; j < 8; j++) {
            int n = bn + tx*8 + j;
            if (n < p.N) {
                float v = acc[i][j];
                if (EPI == 0) v *= p.scale;
                else if (EPI == 1) v = v + p.p0[n];
                else if (EPI == 2) {
                    v = (v + p.p0[n]) * (0.9999950000125f * p.p1[n]) + p.p2[n];
                    v = fmaxf(v, 0.f);
                } else if (EPI == 3) {
                    float d2 = P0[m] + P0[n] - 2.f * v;
                    v = expf(-fmaxf(d2, 0.f) * (1.f/1536.f));
                } else if (EPI == 4) {
                    v = 2.f * P0[(long)m * p.ldc + n] - v;
                }
                Cp[(long)m * p.ldc + n] = v;
            }
        }
    }
}

// ---------------- elementwise / reduction kernels ----------------------------
__global__ void k_build_emb(const float* ge, const float* ue) {
    long i = (long)blockIdx.x * blockDim.x + threadIdx.x;
    if (i >= (long)BB*SN*DF) return;
    int d = i % DF; long bn = i / DF; int n = bn % SN; int b = (int)(bn / SN);
    float x = (n < SIDX) ? ge[((long)b*SIDX + n)*DF + d]
                         : ue[((long)b*SIDX + (n - SIDX))*DF + d];
    int half = d >> 1;
    float freq = expf((float)(2*half) * (-9.210340371976184f/768.f));
    float arg = (float)n * freq;
    float pe = (d & 1) ? cosf(arg) : sinf(arg);
    g_emb[i] = x + pe;
}

__global__ void k_softmax() {
    long row = blockIdx.x;                 // 96*256 rows of length 512
    float* r = g_s + row * SN;
    int tid = threadIdx.x;
    __shared__ float red[256];
    float v0 = r[tid], v1 = r[tid+256];
    red[tid] = fmaxf(v0, v1); __syncthreads();
    for (int s = 128; s > 0; s >>= 1) { if (tid < s) red[tid] = fmaxf(red[tid], red[tid+s]); __syncthreads(); }
    float m = red[0]; __syncthreads();
    float e0 = expf(v0 - m), e1 = expf(v1 - m);
    red[tid] = e0 + e1; __syncthreads();
    for (int s = 128; s > 0; s >>= 1) { if (tid < s) red[tid] += red[tid+s]; __syncthreads(); }
    float inv = 1.f / red[0];
    r[tid] = e0 * inv; r[tid+256] = e1 * inv;
}

__global__ void k_addln(const float* lng, const float* lnb) {
    int row = blockIdx.x;                  // 8*256
    int b = row >> 8, rr = row & 255;
    float*       u  = g_emb + ((long)b*SN + SIDX + rr) * DF;
    const float* mh = g_mha + ((long)b*SIDX + rr) * DF;
    int tid = threadIdx.x;
    __shared__ float red[256];
    float x[3];
#pragma unroll
    for (int t = 0; t < 3; t++) x[t] = u[tid + t*256] + mh[tid + t*256];
    red[tid] = x[0] + x[1] + x[2]; __syncthreads();
    for (int s = 128; s > 0; s >>= 1) { if (tid < s) red[tid] += red[tid+s]; __syncthreads(); }
    float mean = red[0] * (1.f/768.f); __syncthreads();
    float vs = 0.f;
#pragma unroll
    for (int t = 0; t < 3; t++) { float d = x[t] - mean; vs += d*d; }
    red[tid] = vs; __syncthreads();
    for (int s = 128; s > 0; s >>= 1) { if (tid < s) red[tid] += red[tid+s]; __syncthreads(); }
    float inv = rsqrtf(red[0] * (1.f/768.f) + 1e-5f);
#pragma unroll
    for (int t = 0; t < 3; t++) {
        int d = tid + t*256;
        u[d] = (x[t] - mean) * inv * lng[d] + lnb[d];
    }
}

__global__ void k_wprep(const float* c1w, const float* c2w) {
    int i = blockIdx.x * blockDim.x + threadIdx.x;
    if (i < 128*768) {
        int c = i / 768, r = i % 768, k = r / 256, ci = r % 256;
        g_w1r[i] = c1w[(c*256 + ci)*3 + k];
    } else if (i < 128*768 + 128*384) {
        int j = i - 128*768;
        int c = j / 384, r = j % 384, k = r / 128, ci = r % 128;
        g_w2r[j] = c2w[(c*128 + ci)*3 + k];
    }
}

__global__ void k_im2col1() {
    long i = (long)blockIdx.x * blockDim.x + threadIdx.x;
    if (i >= (long)BB*SN*768) return;
    int d = i % 768; long bl = i / 768; int l = bl % SN; int b = (int)(bl / SN);
    int k = d / 256, ci = d % 256;
    int src = l + k - 1;
    g_x1[i] = (src >= 0 && src < SN) ? g_xp[((long)b*SN + src)*PJ + ci] : 0.f;
}

__global__ void k_im2col2() {
    long i = (long)blockIdx.x * blockDim.x + threadIdx.x;
    if (i >= (long)BB*SN*384) return;
    int d = i % 384; long bl = i / 384; int l = bl % SN; int b = (int)(bl / SN);
    int k = d / 128, ci = d % 128;
    int src = l + k - 1;
    g_x2[i] = (src >= 0 && src < SN) ? g_h1[((long)b*SN + src)*HID + ci] : 0.f;
}

__global__ void k_sigma_e(const float* ow, const float* ob) {
    int row = blockIdx.x;                  // 4096 = b*512+n
    int tid = threadIdx.x;
    __shared__ float red[256];
    float part = (tid < HID) ? g_h2[(long)row*HID + tid] * ow[tid] : 0.f;
    red[tid] = part; __syncthreads();
    for (int s = 128; s > 0; s >>= 1) { if (tid < s) red[tid] += red[tid+s]; __syncthreads(); }
    float sig = red[0] + ob[0]; __syncthreads();
    float inv = 1.f / (sig + 1e-6f);
    const float* er = g_emb + (long)row*DF;
    float*       eo = g_e   + (long)row*DF;
    float ss = 0.f;
#pragma unroll
    for (int t = 0; t < 3; t++) {
        float e = er[tid + t*256] * inv;
        eo[tid + t*256] = e;
        ss += e*e;
    }
    red[tid] = ss; __syncthreads();
    for (int s = 128; s > 0; s >>= 1) { if (tid < s) red[tid] += red[tid+s]; __syncthreads(); }
    if (tid == 0) g_sq[row] = red[0];
}

__global__ void k_topk() {
    int row = blockIdx.x * (blockDim.x >> 5) + (threadIdx.x >> 5);  // warp per row
    int lane = threadIdx.x & 31;
    if (row >= BB*SN) return;
    const float* w = g_w + (long)row * SN;
    unsigned char* mk = g_mk + (long)row * SN;
    for (int j = lane; j < SN/4; j += 32) ((unsigned int*)mk)[j] = 0u;
    __syncwarp();
    float v[16];
#pragma unroll
    for (int j = 0; j < 16; j++) v[j] = w[lane + j*32];
    for (int t = 0; t < KTOP; t++) {
        float bm = -1.f; int bj = 0;
#pragma unroll
        for (int j = 0; j < 16; j++) {
            if (v[j] > bm) { bm = v[j]; bj = j; }
        }
        int bidx = lane + bj*32;
#pragma unroll
        for (int s = 16; s > 0; s >>= 1) {
            float om = __shfl_xor_sync(0xffffffffu, bm, s);
            int oi = __shfl_xor_sync(0xffffffffu, bidx, s);
            if (om > bm || (om == bm && oi < bidx)) { bm = om; bidx = oi; }
        }
        if ((bidx & 31) == lane) v[bidx >> 5] = -1.f;
        if (lane == 0) mk[bidx] = 1;
        __syncwarp();
    }
}

__global__ void k_degree() {
    int row = blockIdx.x;                  // 4096
    int b = row >> 9, n = row & 511;
    float* w = g_w + (long)row*SN;
    const unsigned char* mrow = g_mk + (long)row*SN;
    int tid = threadIdx.x;
    __shared__ float red[256];
    float s = 0.f;
    for (int m = tid; m < SN; m += 256) {
        int on = mrow[m] | g_mk[((long)(b*SN + m))*SN + n];
        float val = on ? w[m] : 0.f;
        w[m] = val;
        s += val;
    }
    red[tid] = s; __syncthreads();
    for (int st = 128; st > 0; st >>= 1) { if (tid < st) red[tid] += red[tid+st]; __syncthreads(); }
    if (tid == 0) g_dsi[row] = rsqrtf(red[0] + 1e-6f);
}

__global__ void k_buildA(const float* alpha) {
    long i = (long)blockIdx.x * blockDim.x + threadIdx.x;
    if (i >= (long)BB*SN*SN) return;
    int m = (int)(i % SN); long t = i / SN; int n = (int)(t % SN); int b = (int)(t / SN);
    float a = alpha[0];
    float s = g_dsi[b*SN+n] * g_w[i] * g_dsi[b*SN+m];
    float A = ((n==m) ? 1.f + 1e-6f : 0.f) - a * s;
    g_A[i] = A;
    g_Xa[i] = ((n==m) ? 2.f : 0.f) - A;
}

__global__ void k_scatter(const int* labels, const float* X, float* out) {
    int b = blockIdx.z;
    int m = blockIdx.y;
    int n = blockIdx.x * 128 + threadIdx.x;
    int lab = labels[b*SN + m];
    if (lab >= VOC) return;
    float v = X[((long)(b*SN + m))*SN + n];    // symmetric: prop[b,n,m]
    atomicAdd(out + ((long)(b*SN + n))*VOC + lab, v);
}

// ---------------- host side ---------------------------------------------------
static void run_gemm(int epi, int bt, const GemmP& p, int M, int Z) {
    dim3 g((p.N + 127) / 128, M / 128, Z);
    dim3 b(256);
    if (epi == 0 && bt == 1) gemm_k<0,1><<<g,b>>>(p);
    else if (epi == 0 && bt == 0) gemm_k<0,0><<<g,b>>>(p);
    else if (epi == 1 && bt == 1) gemm_k<1,1><<<g,b>>>(p);
    else if (epi == 2 && bt == 1) gemm_k<2,1><<<g,b>>>(p);
    else if (epi == 3 && bt == 1) gemm_k<3,1><<<g,b>>>(p);
    else if (epi == 4 && bt == 0) gemm_k<4,0><<<g,b>>>(p);
}

extern "C" void kernel_launch(void* const* d_in, const int* in_sizes, int n_in,
                              void* d_out, int out_size) {
    const float* ge    = (const float*)d_in[0];
    const float* ue    = (const float*)d_in[1];
    const float* hs    = (const float*)d_in[2];
    const int*   lab   = (const int*)  d_in[3];
    const float* inw   = (const float*)d_in[4];
    const float* inb   = (const float*)d_in[5];
    const float* outw  = (const float*)d_in[6];
    const float* outb  = (const float*)d_in[7];
    const float* lng   = (const float*)d_in[8];
    const float* lnb   = (const float*)d_in[9];
    const float* pw    = (const float*)d_in[10];
    const float* pb    = (const float*)d_in[11];
    const float* c1w   = (const float*)d_in[12];
    const float* c1b   = (const float*)d_in[13];
    const float* bn1g  = (const float*)d_in[14];
    const float* bn1b  = (const float*)d_in[15];
    const float* c2w   = (const float*)d_in[16];
    const float* c2b   = (const float*)d_in[17];
    const float* bn2g  = (const float*)d_in[18];
    const float* bn2b  = (const float*)d_in[19];
    const float* ow    = (const float*)d_in[20];
    const float* ob    = (const float*)d_in[21];
    const float* alpha = (const float*)d_in[22];
    float* out = (float*)d_out;

    void* vp;
    cudaGetSymbolAddress(&vp, g_emb); float* p_emb = (float*)vp;
    cudaGetSymbolAddress(&vp, g_q);   float* p_q   = (float*)vp;
    cudaGetSymbolAddress(&vp, g_kb);  float* p_kb  = (float*)vp;
    cudaGetSymbolAddress(&vp, g_vb);  float* p_vb  = (float*)vp;
    cudaGetSymbolAddress(&vp, g_s);   float* p_s   = (float*)vp;
    cudaGetSymbolAddress(&vp, g_o);   float* p_o   = (float*)vp;
    cudaGetSymbolAddress(&vp, g_mha); float* p_mha = (float*)vp;
    cudaGetSymbolAddress(&vp, g_xp);  float* p_xp  = (float*)vp;
    cudaGetSymbolAddress(&vp, g_x1);  float* p_x1  = (float*)vp;
    cudaGetSymbolAddress(&vp, g_h1);  float* p_h1  = (float*)vp;
    cudaGetSymbolAddress(&vp, g_x2);  float* p_x2  = (float*)vp;
    cudaGetSymbolAddress(&vp, g_h2);  float* p_h2  = (float*)vp;
    cudaGetSymbolAddress(&vp, g_e);   float* p_e   = (float*)vp;
    cudaGetSymbolAddress(&vp, g_sq);  float* p_sq  = (float*)vp;
    cudaGetSymbolAddress(&vp, g_w);   float* p_w   = (float*)vp;
    cudaGetSymbolAddress(&vp, g_A);   float* p_A   = (float*)vp;
    cudaGetSymbolAddress(&vp, g_Xa);  float* p_Xa  = (float*)vp;
    cudaGetSymbolAddress(&vp, g_Xb);  float* p_Xb  = (float*)vp;
    cudaGetSymbolAddress(&vp, g_T);   float* p_T   = (float*)vp;
    cudaGetSymbolAddress(&vp, g_w1r); float* p_w1r = (float*)vp;
    cudaGetSymbolAddress(&vp, g_w2r); float* p_w2r = (float*)vp;

    // 1. emb = concat + PE ; weight reshapes
    k_build_emb<<<(BB*SN*DF + 255)/256, 256>>>(ge, ue);
    k_wprep<<<(128*768 + 128*384)/256, 256>>>(c1w, c2w);

    GemmP p;
    p.zdiv = 1; p.scale = 1.f;
    p.sA1 = p.sA2 = p.sB1 = p.sB2 = p.sC1 = p.sC2 = p.sP0 = 0;
    p.p0 = p.p1 = p.p2 = 0;

    // 2. Q = u @ wq^T + bq   (batched over b)
    p.A = p_emb + SIDX*DF; p.sA1 = (long)SN*DF; p.lda = DF;
    p.B = inw;             p.ldb = DF;  p.sB1 = 0;
    p.C = p_q;  p.sC1 = (long)SIDX*DF; p.ldc = DF;
    p.N = DF; p.K = DF; p.p0 = inb;
    run_gemm(1, 1, p, SIDX, BB);
    // 3. K, V = hs @ w^T + b (single GEMMs, M=4096)
    p.A = hs; p.sA1 = 0; p.lda = DF;
    p.B = inw + DF*DF;  p.C = p_kb; p.sC1 = 0; p.p0 = inb + DF;
    run_gemm(1, 1, p, BB*SN, 1);
    p.B = inw + 2*DF*DF; p.C = p_vb; p.p0 = inb + 2*DF;
    run_gemm(1, 1, p, BB*SN, 1);

    // 4. scores = Q K^T / 8  (batched over b*h)
    p.zdiv = NH;
    p.A = p_q;  p.sA1 = (long)SIDX*DF; p.sA2 = HD; p.lda = DF;
    p.B = p_kb; p.sB1 = (long)SN*DF;   p.sB2 = HD; p.ldb = DF;
    p.C = p_s;  p.sC1 = (long)NH*SIDX*SN; p.sC2 = (long)SIDX*SN; p.ldc = SN;
    p.N = SN; p.K = HD; p.scale = 0.125f;
    run_gemm(0, 1, p, SIDX, BB*NH);
    // 5. softmax
    k_softmax<<<BB*NH*SIDX, 256>>>();
    // 6. o = attn @ V
    p.A = p_s;  p.sA1 = (long)NH*SIDX*SN; p.sA2 = (long)SIDX*SN; p.lda = SN;
    p.B = p_vb; p.sB1 = (long)SN*DF; p.sB2 = HD; p.ldb = DF;
    p.C = p_o;  p.sC1 = (long)SIDX*DF; p.sC2 = HD; p.ldc = DF;
    p.N = HD; p.K = SN; p.scale = 1.f;
    run_gemm(0, 0, p, SIDX, BB*NH);
    // 7. mha = o @ out_w^T + out_b
    p.zdiv = 1; p.sA1 = p.sA2 = p.sB1 = p.sB2 = p.sC1 = p.sC2 = 0;
    p.A = p_o; p.lda = DF; p.B = outw; p.ldb = DF;
    p.C = p_mha; p.ldc = DF; p.N = DF; p.K = DF; p.p0 = outb;
    run_gemm(1, 1, p, BB*SIDX, 1);
    // 8. u = LN(u + mha) in place
    k_addln<<<BB*SIDX, 256>>>(lng, lnb);
    // 9. xp = emb @ proj_w^T + proj_b
    p.A = p_emb; p.lda = DF; p.B = pw; p.ldb = DF;
    p.C = p_xp; p.ldc = PJ; p.N = PJ; p.K = DF; p.p0 = pb;
    run_gemm(1, 1, p, BB*SN, 1);
    // 10. conv1 + bn + relu
    k_im2col1<<<(BB*SN*768 + 255)/256, 256>>>();
    p.A = p_x1; p.lda = 768; p.B = p_w1r; p.ldb = 768;
    p.C = p_h1; p.ldc = HID; p.N = HID; p.K = 768;
    p.p0 = c1b; p.p1 = bn1g; p.p2 = bn1b;
    run_gemm(2, 1, p, BB*SN, 1);
    // 11. conv2 + bn + relu
    k_im2col2<<<(BB*SN*384 + 255)/256, 256>>>();
    p.A = p_x2; p.lda = 384; p.B = p_w2r; p.ldb = 384;
    p.C = p_h2; p.ldc = HID; p.N = HID; p.K = 384;
    p.p0 = c2b; p.p1 = bn2g; p.p2 = bn2b;
    run_gemm(2, 1, p, BB*SN, 1);
    // 12. sigma, e, sq
    k_sigma_e<<<BB*SN, 256>>>(ow, ob);
    // 13. W = exp(-(d2/768)/2)  via Gram + epilogue (batched over b)
    p.A = p_e; p.sA1 = (long)SN*DF; p.lda = DF;
    p.B = p_e; p.sB1 = (long)SN*DF; p.ldb = DF;
    p.C = p_w; p.sC1 = (long)SN*SN; p.ldc = SN;
    p.N = SN; p.K = DF; p.p0 = p_sq; p.sP0 = SN;
    run_gemm(3, 1, p, SN, BB);
    // 14. top-k mask, symmetrize+degree, build A and X1=2I-A
    k_topk<<<BB*SN/4, 128>>>();
    k_degree<<<BB*SN, 256>>>();
    k_buildA<<<(BB*SN*SN + 255)/256, 256>>>(alpha);
    // 15. Newton-Schulz: X <- 2X - X(AX), 9 iters (X1 = 2I - A already)
    //     residual after: rho^(2^10) = 0.98^512 ~ 3e-5  << 1e-3 tolerance
    float* Xc = p_Xa; float* Xn = p_Xb;
    for (int it = 0; it < 9; it++) {
        // T = A @ Xc
        p.A = p_A;  p.sA1 = (long)SN*SN; p.lda = SN;
        p.B = Xc;   p.sB1 = (long)SN*SN; p.sB2 = 0; p.ldb = SN;
        p.C = p_T;  p.sC1 = (long)SN*SN; p.ldc = SN;
        p.N = SN; p.K = SN; p.scale = 1.f; p.sP0 = 0; p.p0 = 0;
        run_gemm(0, 0, p, SN, BB);
        // Xn = 2*Xc - Xc @ T
        p.A = Xc; p.B = p_T; p.C = Xn;
        p.p0 = Xc; p.sP0 = (long)SN*SN;
        run_gemm(4, 0, p, SN, BB);
        float* t = Xc; Xc = Xn; Xn = t;
    }
    // 16. out = prop @ one_hot(labels): zero + scatter (prop symmetric)
    cudaMemsetAsync(out, 0, (size_t)out_size * sizeof(float));
    dim3 sg(SN/128, SN, BB);
    k_scatter<<<sg, 128>>>(lab, Xc, out);
}

// round 5
// speedup vs baseline: 1.3062x; 1.3062x over previous
#include <cuda_runtime.h>
#include <math.h>

#define BB 8
#define SN 512
#define SIDX 256
#define DF 768
#define NH 12
#define HD 64
#define PJ 256
#define HID 128
#define VOC 16384
#define KTOP 20

// ---------------- scratch (static device globals; no allocations) ------------
__device__ float g_emb[BB*SN*DF];
__device__ float g_q  [BB*SIDX*DF];
__device__ float g_kb [BB*SN*DF];
__device__ float g_vb [BB*SN*DF];
__device__ float g_s  [BB*NH*SIDX*SN];
__device__ float g_o  [BB*SIDX*DF];
__device__ float g_mha[BB*SIDX*DF];
__device__ float g_xp [BB*SN*PJ];
__device__ float g_x1 [BB*SN*768];
__device__ float g_h1 [BB*SN*HID];
__device__ float g_x2 [BB*SN*384];
__device__ float g_h2 [BB*SN*HID];
__device__ float g_e  [BB*SN*DF];
__device__ float g_sq [BB*SN];
__device__ float g_w  [BB*SN*SN];
__device__ unsigned char g_mk[BB*SN*SN];
__device__ float g_dsi[BB*SN];
__device__ float g_A  [BB*SN*SN];
__device__ float g_Xa [BB*SN*SN];
__device__ float g_Xb [BB*SN*SN];
__device__ float g_T  [BB*SN*SN];
__device__ float g_w1r[HID*768];
__device__ float g_w2r[HID*384];

// ---------------- generic batched GEMM (SIMT, R2 version) ---------------------
struct GemmP {
    const float* A; const float* B; float* C;
    int N, K, lda, ldb, ldc, zdiv;
    long sA1, sA2, sB1, sB2, sC1, sC2, sP0;
    float scale;
    const float* p0; const float* p1; const float* p2;
};

template<int EPI, int BT>
__global__ void __launch_bounds__(256) gemm_k(GemmP p) {
    __shared__ float As[16][128];
    __shared__ float Bs[16][128];
    int z  = blockIdx.z;
    int zb = z / p.zdiv, zr = z % p.zdiv;
    const float* Ap = p.A + zb * p.sA1 + (long)zr * p.sA2;
    const float* Bp = p.B + zb * p.sB1 + (long)zr * p.sB2;
    float*       Cp = p.C + zb * p.sC1 + (long)zr * p.sC2;
    int bm = blockIdx.y * 128, bn = blockIdx.x * 128;
    int tid = threadIdx.x;
    int tx = tid & 15, ty = tid >> 4;
    float acc[8][8];
#pragma unroll
    for (int i = 0; i < 8; i++)
#pragma unroll
        for (int j = 0; j < 8; j++) acc[i][j] = 0.f;

    for (int k0 = 0; k0 < p.K; k0 += 16) {
        __syncthreads();
#pragma unroll
        for (int f = 0; f < 2; f++) {          // A tile: 128 x 16
            int idx = tid + f * 256;
            int r = idx >> 2, c4 = (idx & 3) * 4;
            float4 v = *(const float4*)(Ap + (long)(bm + r) * p.lda + k0 + c4);
            As[c4+0][r] = v.x; As[c4+1][r] = v.y; As[c4+2][r] = v.z; As[c4+3][r] = v.w;
        }
        if (BT) {
#pragma unroll
            for (int f = 0; f < 2; f++) {      // B tile (NT): rows are n
                int idx = tid + f * 256;
                int r = idx >> 2, c4 = (idx & 3) * 4;
                int n = bn + r;
                float4 v = make_float4(0.f,0.f,0.f,0.f);
                if (n < p.N) v = *(const float4*)(Bp + (long)n * p.ldb + k0 + c4);
                Bs[c4+0][r] = v.x; Bs[c4+1][r] = v.y; Bs[c4+2][r] = v.z; Bs[c4+3][r] = v.w;
            }
        } else {
#pragma unroll
            for (int f = 0; f < 2; f++) {      // B tile (NN): 16 x 128
                int idx = tid + f * 256;
                int kr = idx >> 5, c = (idx & 31) * 4;
                int n = bn + c;
                float4 v = make_float4(0.f,0.f,0.f,0.f);
                if (n < p.N) v = *(const float4*)(Bp + (long)(k0 + kr) * p.ldb + n);
                *(float4*)&Bs[kr][c] = v;
            }
        }
        __syncthreads();
#pragma unroll
        for (int kk = 0; kk < 16; kk++) {
            float4 a0 = *(float4*)&As[kk][ty*8];
            float4 a1 = *(float4*)&As[kk][ty*8+4];
            float4 b0 = *(float4*)&Bs[kk][tx*8];
            float4 b1 = *(float4*)&Bs[kk][tx*8+4];
            float av[8] = {a0.x,a0.y,a0.z,a0.w,a1.x,a1.y,a1.z,a1.w};
            float bv[8] = {b0.x,b0.y,b0.z,b0.w,b1.x,b1.y,b1.z,b1.w};
#pragma unroll
            for (int i = 0; i < 8; i++)
#pragma unroll
                for (int j = 0; j < 8; j++) acc[i][j] += av[i]*bv[j];
        }
    }

    const float* P0 = p.p0;
    if (EPI == 3) P0 = p.p0 + zb * p.sP0;
#pragma unroll
    for (int i = 0; i < 8; i++) {
        int m = bm + ty*8 + i;
#pragma unroll
        for (int j = 0; j < 8; j++) {
            int n = bn + tx*8 + j;
            if (n < p.N) {
                float v = acc[i][j];
                if (EPI == 0) v *= p.scale;
                else if (EPI == 1) v = v + p.p0[n];
                else if (EPI == 2) {
                    v = (v + p.p0[n]) * (0.9999950000125f * p.p1[n]) + p.p2[n];
                    v = fmaxf(v, 0.f);
                } else if (EPI == 3) {
                    float d2 = P0[m] + P0[n] - 2.f * v;
                    v = expf(-fmaxf(d2, 0.f) * (1.f/1536.f));
                }
                Cp[(long)m * p.ldc + n] = v;
            }
        }
    }
}

// ---------------- tensor-core Newton GEMM (split-tf32) ------------------------
// C = epi( A[512x512] @ B[512x512] ), batch = blockIdx.z, all row-major.
// EPI 0: C = acc ; EPI 4: C = 2*X - acc
__device__ __forceinline__ float tf32hi(float x) {
    return __uint_as_float(__float_as_uint(x) & 0xFFFFE000u);
}
__device__ __forceinline__ void mma8(float* d, const unsigned* a, const unsigned* b) {
    asm volatile("mma.sync.aligned.m16n8k8.row.col.f32.tf32.tf32.f32 "
        "{%0,%1,%2,%3}, {%4,%5,%6,%7}, {%8,%9}, {%0,%1,%2,%3};"
        : "+f"(d[0]), "+f"(d[1]), "+f"(d[2]), "+f"(d[3])
        : "r"(a[0]), "r"(a[1]), "r"(a[2]), "r"(a[3]), "r"(b[0]), "r"(b[1]));
}

template<int EPI>
__global__ void __launch_bounds__(128) ngemm_k(const float* __restrict__ A,
                                               const float* __restrict__ B,
                                               float* __restrict__ C,
                                               const float* __restrict__ X) {
    __shared__ float Ah[64*36], Al[64*36];
    __shared__ float Bh[32*68], Bl[32*68];
    int z = blockIdx.z;
    const float* Ap = A + (long)z*SN*SN + (long)blockIdx.y*64*SN;
    const float* Bp = B + (long)z*SN*SN + blockIdx.x*64;
    float*       Cp = C + (long)z*SN*SN + (long)blockIdx.y*64*SN + blockIdx.x*64;
    const float* Xp = X + (long)z*SN*SN + (long)blockIdx.y*64*SN + blockIdx.x*64;
    int tid = threadIdx.x;
    int warp = tid >> 5, lane = tid & 31;
    int g = lane >> 2, t = lane & 3;
    int m0 = (warp >> 1) * 32, n0 = (warp & 1) * 32;

    float acc[2][4][4];
#pragma unroll
    for (int i = 0; i < 2; i++)
#pragma unroll
        for (int j = 0; j < 4; j++)
#pragma unroll
            for (int r = 0; r < 4; r++) acc[i][j][r] = 0.f;

    for (int k0 = 0; k0 < SN; k0 += 32) {
        __syncthreads();
#pragma unroll
        for (int f = 0; f < 4; f++) {
            int s = tid + f * 128;
            {   // A tile: 64 rows x 32 k
                int r = s >> 3, c4 = (s & 7) * 4;
                float4 v = *(const float4*)(Ap + (long)r * SN + k0 + c4);
                float4 h, l;
                h.x = tf32hi(v.x); l.x = v.x - h.x;
                h.y = tf32hi(v.y); l.y = v.y - h.y;
                h.z = tf32hi(v.z); l.z = v.z - h.z;
                h.w = tf32hi(v.w); l.w = v.w - h.w;
                *(float4*)&Ah[r*36 + c4] = h;
                *(float4*)&Al[r*36 + c4] = l;
            }
            {   // B tile: 32 k x 64 n
                int k = s >> 4, c4 = (s & 15) * 4;
                float4 v = *(const float4*)(Bp + (long)(k0 + k) * SN + c4);
                float4 h, l;
                h.x = tf32hi(v.x); l.x = v.x - h.x;
                h.y = tf32hi(v.y); l.y = v.y - h.y;
                h.z = tf32hi(v.z); l.z = v.z - h.z;
                h.w = tf32hi(v.w); l.w = v.w - h.w;
                *(float4*)&Bh[k*68 + c4] = h;
                *(float4*)&Bl[k*68 + c4] = l;
            }
        }
        __syncthreads();
#pragma unroll
        for (int ks = 0; ks < 4; ks++) {
            int kb = ks * 8;
            unsigned ah[2][4], al[2][4], bh[4][2], bl[4][2];
#pragma unroll
            for (int i = 0; i < 2; i++) {
                int mb = m0 + i*16;
                ah[i][0] = __float_as_uint(Ah[(mb + g    )*36 + kb + t    ]);
                ah[i][1] = __float_as_uint(Ah[(mb + 8 + g)*36 + kb + t    ]);
                ah[i][2] = __float_as_uint(Ah[(mb + g    )*36 + kb + t + 4]);
                ah[i][3] = __float_as_uint(Ah[(mb + 8 + g)*36 + kb + t + 4]);
                al[i][0] = __float_as_uint(Al[(mb + g    )*36 + kb + t    ]);
                al[i][1] = __float_as_uint(Al[(mb + 8 + g)*36 + kb + t    ]);
                al[i][2] = __float_as_uint(Al[(mb + g    )*36 + kb + t + 4]);
                al[i][3] = __float_as_uint(Al[(mb + 8 + g)*36 + kb + t + 4]);
            }
#pragma unroll
            for (int j = 0; j < 4; j++) {
                int nb = n0 + j*8 + g;
                bh[j][0] = __float_as_uint(Bh[(kb + t    )*68 + nb]);
                bh[j][1] = __float_as_uint(Bh[(kb + t + 4)*68 + nb]);
                bl[j][0] = __float_as_uint(Bl[(kb + t    )*68 + nb]);
                bl[j][1] = __float_as_uint(Bl[(kb + t + 4)*68 + nb]);
            }
#pragma unroll
            for (int i = 0; i < 2; i++)
#pragma unroll
                for (int j = 0; j < 4; j++) {
                    mma8(acc[i][j], ah[i], bh[j]);
                    mma8(acc[i][j], ah[i], bl[j]);
                    mma8(acc[i][j], al[i], bh[j]);
                }
        }
    }

#pragma unroll
    for (int i = 0; i < 2; i++)
#pragma unroll
        for (int j = 0; j < 4; j++) {
            int m = m0 + i*16 + g;
            int n = n0 + j*8 + 2*t;
            float v0 = acc[i][j][0], v1 = acc[i][j][1];
            float v2 = acc[i][j][2], v3 = acc[i][j][3];
            if (EPI == 4) {
                v0 = 2.f * Xp[(long)m*SN + n]     - v0;
                v1 = 2.f * Xp[(long)m*SN + n + 1] - v1;
                v2 = 2.f * Xp[(long)(m+8)*SN + n]     - v2;
                v3 = 2.f * Xp[(long)(m+8)*SN + n + 1] - v3;
            }
            Cp[(long)m*SN + n]     = v0;
            Cp[(long)m*SN + n + 1] = v1;
            Cp[(long)(m+8)*SN + n]     = v2;
            Cp[(long)(m+8)*SN + n + 1] = v3;
        }
}

// ---------------- elementwise / reduction kernels ----------------------------
__global__ void k_build_emb(const float* ge, const float* ue) {
    long i = (long)blockIdx.x * blockDim.x + threadIdx.x;
    if (i >= (long)BB*SN*DF) return;
    int d = i % DF; long bn = i / DF; int n = bn % SN; int b = (int)(bn / SN);
    float x = (n < SIDX) ? ge[((long)b*SIDX + n)*DF + d]
                         : ue[((long)b*SIDX + (n - SIDX))*DF + d];
    int half = d >> 1;
    float freq = expf((float)(2*half) * (-9.210340371976184f/768.f));
    float arg = (float)n * freq;
    float pe = (d & 1) ? cosf(arg) : sinf(arg);
    g_emb[i] = x + pe;
}

__global__ void k_softmax() {
    long row = blockIdx.x;
    float* r = g_s + row * SN;
    int tid = threadIdx.x;
    __shared__ float red[256];
    float v0 = r[tid], v1 = r[tid+256];
    red[tid] = fmaxf(v0, v1); __syncthreads();
    for (int s = 128; s > 0; s >>= 1) { if (tid < s) red[tid] = fmaxf(red[tid], red[tid+s]); __syncthreads(); }
    float m = red[0]; __syncthreads();
    float e0 = expf(v0 - m), e1 = expf(v1 - m);
    red[tid] = e0 + e1; __syncthreads();
    for (int s = 128; s > 0; s >>= 1) { if (tid < s) red[tid] += red[tid+s]; __syncthreads(); }
    float inv = 1.f / red[0];
    r[tid] = e0 * inv; r[tid+256] = e1 * inv;
}

__global__ void k_addln(const float* lng, const float* lnb) {
    int row = blockIdx.x;
    int b = row >> 8, rr = row & 255;
    float*       u  = g_emb + ((long)b*SN + SIDX + rr) * DF;
    const float* mh = g_mha + ((long)b*SIDX + rr) * DF;
    int tid = threadIdx.x;
    __shared__ float red[256];
    float x[3];
#pragma unroll
    for (int t = 0; t < 3; t++) x[t] = u[tid + t*256] + mh[tid + t*256];
    red[tid] = x[0] + x[1] + x[2]; __syncthreads();
    for (int s = 128; s > 0; s >>= 1) { if (tid < s) red[tid] += red[tid+s]; __syncthreads(); }
    float mean = red[0] * (1.f/768.f); __syncthreads();
    float vs = 0.f;
#pragma unroll
    for (int t = 0; t < 3; t++) { float d = x[t] - mean; vs += d*d; }
    red[tid] = vs; __syncthreads();
    for (int s = 128; s > 0; s >>= 1) { if (tid < s) red[tid] += red[tid+s]; __syncthreads(); }
    float inv = rsqrtf(red[0] * (1.f/768.f) + 1e-5f);
#pragma unroll
    for (int t = 0; t < 3; t++) {
        int d = tid + t*256;
        u[d] = (x[t] - mean) * inv * lng[d] + lnb[d];
    }
}

__global__ void k_wprep(const float* c1w, const float* c2w) {
    int i = blockIdx.x * blockDim.x + threadIdx.x;
    if (i < 128*768) {
        int c = i / 768, r = i % 768, k = r / 256, ci = r % 256;
        g_w1r[i] = c1w[(c*256 + ci)*3 + k];
    } else if (i < 128*768 + 128*384) {
        int j = i - 128*768;
        int c = j / 384, r = j % 384, k = r / 128, ci = r % 128;
        g_w2r[j] = c2w[(c*128 + ci)*3 + k];
    }
}

__global__ void k_im2col1() {
    long i = (long)blockIdx.x * blockDim.x + threadIdx.x;
    if (i >= (long)BB*SN*768) return;
    int d = i % 768; long bl = i / 768; int l = bl % SN; int b = (int)(bl / SN);
    int k = d / 256, ci = d % 256;
    int src = l + k - 1;
    g_x1[i] = (src >= 0 && src < SN) ? g_xp[((long)b*SN + src)*PJ + ci] : 0.f;
}

__global__ void k_im2col2() {
    long i = (long)blockIdx.x * blockDim.x + threadIdx.x;
    if (i >= (long)BB*SN*384) return;
    int d = i % 384; long bl = i / 384; int l = bl % SN; int b = (int)(bl / SN);
    int k = d / 128, ci = d % 128;
    int src = l + k - 1;
    g_x2[i] = (src >= 0 && src < SN) ? g_h1[((long)b*SN + src)*HID + ci] : 0.f;
}

__global__ void k_sigma_e(const float* ow, const float* ob) {
    int row = blockIdx.x;
    int tid = threadIdx.x;
    __shared__ float red[256];
    float part = (tid < HID) ? g_h2[(long)row*HID + tid] * ow[tid] : 0.f;
    red[tid] = part; __syncthreads();
    for (int s = 128; s > 0; s >>= 1) { if (tid < s) red[tid] += red[tid+s]; __syncthreads(); }
    float sig = red[0] + ob[0]; __syncthreads();
    float inv = 1.f / (sig + 1e-6f);
    const float* er = g_emb + (long)row*DF;
    float*       eo = g_e   + (long)row*DF;
    float ss = 0.f;
#pragma unroll
    for (int t = 0; t < 3; t++) {
        float e = er[tid + t*256] * inv;
        eo[tid + t*256] = e;
        ss += e*e;
    }
    red[tid] = ss; __syncthreads();
    for (int s = 128; s > 0; s >>= 1) { if (tid < s) red[tid] += red[tid+s]; __syncthreads(); }
    if (tid == 0) g_sq[row] = red[0];
}

__global__ void k_topk() {
    int row = blockIdx.x * (blockDim.x >> 5) + (threadIdx.x >> 5);
    int lane = threadIdx.x & 31;
    if (row >= BB*SN) return;
    const float* w = g_w + (long)row * SN;
    unsigned char* mk = g_mk + (long)row * SN;
    for (int j = lane; j < SN/4; j += 32) ((unsigned int*)mk)[j] = 0u;
    __syncwarp();
    float v[16];
#pragma unroll
    for (int j = 0; j < 16; j++) v[j] = w[lane + j*32];
    for (int t = 0; t < KTOP; t++) {
        float bm = -1.f; int bj = 0;
#pragma unroll
        for (int j = 0; j < 16; j++) {
            if (v[j] > bm) { bm = v[j]; bj = j; }
        }
        int bidx = lane + bj*32;
#pragma unroll
        for (int s = 16; s > 0; s >>= 1) {
            float om = __shfl_xor_sync(0xffffffffu, bm, s);
            int oi = __shfl_xor_sync(0xffffffffu, bidx, s);
            if (om > bm || (om == bm && oi < bidx)) { bm = om; bidx = oi; }
        }
        if ((bidx & 31) == lane) v[bidx >> 5] = -1.f;
        if (lane == 0) mk[bidx] = 1;
        __syncwarp();
    }
}

__global__ void k_degree() {
    int row = blockIdx.x;
    int b = row >> 9, n = row & 511;
    float* w = g_w + (long)row*SN;
    const unsigned char* mrow = g_mk + (long)row*SN;
    int tid = threadIdx.x;
    __shared__ float red[256];
    float s = 0.f;
    for (int m = tid; m < SN; m += 256) {
        int on = mrow[m] | g_mk[((long)(b*SN + m))*SN + n];
        float val = on ? w[m] : 0.f;
        w[m] = val;
        s += val;
    }
    red[tid] = s; __syncthreads();
    for (int st = 128; st > 0; st >>= 1) { if (tid < st) red[tid] += red[tid+st]; __syncthreads(); }
    if (tid == 0) g_dsi[row] = rsqrtf(red[0] + 1e-6f);
}

__global__ void k_buildA(const float* alpha) {
    long i = (long)blockIdx.x * blockDim.x + threadIdx.x;
    if (i >= (long)BB*SN*SN) return;
    int m = (int)(i % SN); long t = i / SN; int n = (int)(t % SN); int b = (int)(t / SN);
    float a = alpha[0];
    float s = g_dsi[b*SN+n] * g_w[i] * g_dsi[b*SN+m];
    float A = ((n==m) ? 1.f + 1e-6f : 0.f) - a * s;
    g_A[i] = A;
    g_Xa[i] = ((n==m) ? 2.f : 0.f) - A;
}

__global__ void k_scatter(const int* labels, const float* X, float* out) {
    int b = blockIdx.z;
    int m = blockIdx.y;
    int n = blockIdx.x * 128 + threadIdx.x;
    int lab = labels[b*SN + m];
    if (lab >= VOC) return;
    float v = X[((long)(b*SN + m))*SN + n];    // symmetric: prop[b,n,m]
    atomicAdd(out + ((long)(b*SN + n))*VOC + lab, v);
}

// ---------------- host side ---------------------------------------------------
static void run_gemm(int epi, int bt, const GemmP& p, int M, int Z) {
    dim3 g((p.N + 127) / 128, M / 128, Z);
    dim3 b(256);
    if (epi == 0 && bt == 1) gemm_k<0,1><<<g,b>>>(p);
    else if (epi == 0 && bt == 0) gemm_k<0,0><<<g,b>>>(p);
    else if (epi == 1 && bt == 1) gemm_k<1,1><<<g,b>>>(p);
    else if (epi == 2 && bt == 1) gemm_k<2,1><<<g,b>>>(p);
    else if (epi == 3 && bt == 1) gemm_k<3,1><<<g,b>>>(p);
}

extern "C" void kernel_launch(void* const* d_in, const int* in_sizes, int n_in,
                              void* d_out, int out_size) {
    const float* ge    = (const float*)d_in[0];
    const float* ue    = (const float*)d_in[1];
    const float* hs    = (const float*)d_in[2];
    const int*   lab   = (const int*)  d_in[3];
    const float* inw   = (const float*)d_in[4];
    const float* inb   = (const float*)d_in[5];
    const float* outw  = (const float*)d_in[6];
    const float* outb  = (const float*)d_in[7];
    const float* lng   = (const float*)d_in[8];
    const float* lnb   = (const float*)d_in[9];
    const float* pw    = (const float*)d_in[10];
    const float* pb    = (const float*)d_in[11];
    const float* c1w   = (const float*)d_in[12];
    const float* c1b   = (const float*)d_in[13];
    const float* bn1g  = (const float*)d_in[14];
    const float* bn1b  = (const float*)d_in[15];
    const float* c2w   = (const float*)d_in[16];
    const float* c2b   = (const float*)d_in[17];
    const float* bn2g  = (const float*)d_in[18];
    const float* bn2b  = (const float*)d_in[19];
    const float* ow    = (const float*)d_in[20];
    const float* ob    = (const float*)d_in[21];
    const float* alpha = (const float*)d_in[22];
    float* out = (float*)d_out;

    void* vp;
    cudaGetSymbolAddress(&vp, g_emb); float* p_emb = (float*)vp;
    cudaGetSymbolAddress(&vp, g_q);   float* p_q   = (float*)vp;
    cudaGetSymbolAddress(&vp, g_kb);  float* p_kb  = (float*)vp;
    cudaGetSymbolAddress(&vp, g_vb);  float* p_vb  = (float*)vp;
    cudaGetSymbolAddress(&vp, g_s);   float* p_s   = (float*)vp;
    cudaGetSymbolAddress(&vp, g_o);   float* p_o   = (float*)vp;
    cudaGetSymbolAddress(&vp, g_mha); float* p_mha = (float*)vp;
    cudaGetSymbolAddress(&vp, g_xp);  float* p_xp  = (float*)vp;
    cudaGetSymbolAddress(&vp, g_x1);  float* p_x1  = (float*)vp;
    cudaGetSymbolAddress(&vp, g_h1);  float* p_h1  = (float*)vp;
    cudaGetSymbolAddress(&vp, g_x2);  float* p_x2  = (float*)vp;
    cudaGetSymbolAddress(&vp, g_h2);  float* p_h2  = (float*)vp;
    cudaGetSymbolAddress(&vp, g_e);   float* p_e   = (float*)vp;
    cudaGetSymbolAddress(&vp, g_sq);  float* p_sq  = (float*)vp;
    cudaGetSymbolAddress(&vp, g_w);   float* p_w   = (float*)vp;
    cudaGetSymbolAddress(&vp, g_A);   float* p_A   = (float*)vp;
    cudaGetSymbolAddress(&vp, g_Xa);  float* p_Xa  = (float*)vp;
    cudaGetSymbolAddress(&vp, g_Xb);  float* p_Xb  = (float*)vp;
    cudaGetSymbolAddress(&vp, g_T);   float* p_T   = (float*)vp;
    cudaGetSymbolAddress(&vp, g_w1r); float* p_w1r = (float*)vp;
    cudaGetSymbolAddress(&vp, g_w2r); float* p_w2r = (float*)vp;

    // 1. emb = concat + PE ; weight reshapes
    k_build_emb<<<(BB*SN*DF + 255)/256, 256>>>(ge, ue);
    k_wprep<<<(128*768 + 128*384)/256, 256>>>(c1w, c2w);

    GemmP p;
    p.zdiv = 1; p.scale = 1.f;
    p.sA1 = p.sA2 = p.sB1 = p.sB2 = p.sC1 = p.sC2 = p.sP0 = 0;
    p.p0 = p.p1 = p.p2 = 0;

    // 2. Q = u @ wq^T + bq
    p.A = p_emb + SIDX*DF; p.sA1 = (long)SN*DF; p.lda = DF;
    p.B = inw;             p.ldb = DF;  p.sB1 = 0;
    p.C = p_q;  p.sC1 = (long)SIDX*DF; p.ldc = DF;
    p.N = DF; p.K = DF; p.p0 = inb;
    run_gemm(1, 1, p, SIDX, BB);
    // 3. K, V = hs @ w^T + b
    p.A = hs; p.sA1 = 0; p.lda = DF;
    p.B = inw + DF*DF;  p.C = p_kb; p.sC1 = 0; p.p0 = inb + DF;
    run_gemm(1, 1, p, BB*SN, 1);
    p.B = inw + 2*DF*DF; p.C = p_vb; p.p0 = inb + 2*DF;
    run_gemm(1, 1, p, BB*SN, 1);

    // 4. scores = Q K^T / 8
    p.zdiv = NH;
    p.A = p_q;  p.sA1 = (long)SIDX*DF; p.sA2 = HD; p.lda = DF;
    p.B = p_kb; p.sB1 = (long)SN*DF;   p.sB2 = HD; p.ldb = DF;
    p.C = p_s;  p.sC1 = (long)NH*SIDX*SN; p.sC2 = (long)SIDX*SN; p.ldc = SN;
    p.N = SN; p.K = HD; p.scale = 0.125f;
    run_gemm(0, 1, p, SIDX, BB*NH);
    // 5. softmax
    k_softmax<<<BB*NH*SIDX, 256>>>();
    // 6. o = attn @ V
    p.A = p_s;  p.sA1 = (long)NH*SIDX*SN; p.sA2 = (long)SIDX*SN; p.lda = SN;
    p.B = p_vb; p.sB1 = (long)SN*DF; p.sB2 = HD; p.ldb = DF;
    p.C = p_o;  p.sC1 = (long)SIDX*DF; p.sC2 = HD; p.ldc = DF;
    p.N = HD; p.K = SN; p.scale = 1.f;
    run_gemm(0, 0, p, SIDX, BB*NH);
    // 7. mha = o @ out_w^T + out_b
    p.zdiv = 1; p.sA1 = p.sA2 = p.sB1 = p.sB2 = p.sC1 = p.sC2 = 0;
    p.A = p_o; p.lda = DF; p.B = outw; p.ldb = DF;
    p.C = p_mha; p.ldc = DF; p.N = DF; p.K = DF; p.p0 = outb;
    run_gemm(1, 1, p, BB*SIDX, 1);
    // 8. u = LN(u + mha)
    k_addln<<<BB*SIDX, 256>>>(lng, lnb);
    // 9. xp = emb @ proj_w^T + proj_b
    p.A = p_emb; p.lda = DF; p.B = pw; p.ldb = DF;
    p.C = p_xp; p.ldc = PJ; p.N = PJ; p.K = DF; p.p0 = pb;
    run_gemm(1, 1, p, BB*SN, 1);
    // 10. conv1 + bn + relu
    k_im2col1<<<(BB*SN*768 + 255)/256, 256>>>();
    p.A = p_x1; p.lda = 768; p.B = p_w1r; p.ldb = 768;
    p.C = p_h1; p.ldc = HID; p.N = HID; p.K = 768;
    p.p0 = c1b; p.p1 = bn1g; p.p2 = bn1b;
    run_gemm(2, 1, p, BB*SN, 1);
    // 11. conv2 + bn + relu
    k_im2col2<<<(BB*SN*384 + 255)/256, 256>>>();
    p.A = p_x2; p.lda = 384; p.B = p_w2r; p.ldb = 384;
    p.C = p_h2; p.ldc = HID; p.N = HID; p.K = 384;
    p.p0 = c2b; p.p1 = bn2g; p.p2 = bn2b;
    run_gemm(2, 1, p, BB*SN, 1);
    // 12. sigma, e, sq
    k_sigma_e<<<BB*SN, 256>>>(ow, ob);
    // 13. W = exp(-(d2/768)/2)
    p.A = p_e; p.sA1 = (long)SN*DF; p.lda = DF;
    p.B = p_e; p.sB1 = (long)SN*DF; p.ldb = DF;
    p.C = p_w; p.sC1 = (long)SN*SN; p.ldc = SN;
    p.N = SN; p.K = DF; p.p0 = p_sq; p.sP0 = SN;
    run_gemm(3, 1, p, SN, BB);
    // 14. top-k mask, symmetrize+degree, build A and X1=2I-A
    k_topk<<<BB*SN/4, 128>>>();
    k_degree<<<BB*SN, 256>>>();
    k_buildA<<<(BB*SN*SN + 255)/256, 256>>>(alpha);
    // 15. Newton-Schulz on tensor cores: X <- 2X - X(AX), 9 iters
    float* Xc = p_Xa; float* Xn = p_Xb;
    dim3 ng(8, 8, BB);
    for (int it = 0; it < 9; it++) {
        ngemm_k<0><<<ng, 128>>>(p_A, Xc, p_T, Xc);       // T = A @ Xc
        ngemm_k<4><<<ng, 128>>>(Xc, p_T, Xn, Xc);        // Xn = 2*Xc - Xc @ T
        float* t = Xc; Xc = Xn; Xn = t;
    }
    // 16. out = prop @ one_hot(labels): zero + scatter (prop symmetric)
    cudaMemsetAsync(out, 0, (size_t)out_size * sizeof(float));
    dim3 sg(SN/128, SN, BB);
    k_scatter<<<sg, 128>>>(lab, Xc, out);
}

// round 7
// speedup vs baseline: 1.9533x; 1.4954x over previous
#include <cuda_runtime.h>
#include <math.h>

#define BB 8
#define SN 512
#define SIDX 256
#define DF 768
#define NH 12
#define HD 64
#define PJ 256
#define HID 128
#define VOC 16384
#define KTOP 20

#define ASTR 20     // A smem row stride (m-major, 16 k + pad)
#define BSTR1 20    // B smem row stride, BT=1 ([n][k])
#define BSTR0 68    // B smem row stride, BT=0 ([k][n])

// ---------------- scratch (static device globals; no allocations) ------------
__device__ float g_emb[BB*SN*DF];
__device__ float g_q  [BB*SIDX*DF];
__device__ float g_kb [BB*SN*DF];
__device__ float g_vb [BB*SN*DF];
__device__ float g_s  [BB*NH*SIDX*SN];
__device__ float g_o  [BB*SIDX*DF];
__device__ float g_mha[BB*SIDX*DF];
__device__ float g_xp [BB*SN*PJ];
__device__ float g_x1 [BB*SN*768];
__device__ float g_h1 [BB*SN*HID];
__device__ float g_x2 [BB*SN*384];
__device__ float g_h2 [BB*SN*HID];
__device__ float g_e  [BB*SN*DF];
__device__ float g_sq [BB*SN];
__device__ float g_w  [BB*SN*SN];
__device__ unsigned char g_mk[BB*SN*SN];
__device__ float g_dsi[BB*SN];
__device__ float g_A  [BB*SN*SN];
__device__ float g_Xa [BB*SN*SN];
__device__ float g_Xb [BB*SN*SN];
__device__ float g_T  [BB*SN*SN];
__device__ float g_w1r[HID*768];
__device__ float g_w2r[HID*384];

// ---------------- unified tensor-core GEMM (split-tf32, cp.async) -------------
// C = epi( A(MxK) * op(B) ) ; BT=1: B is [N,K] (C=A*B^T), BT=0: B is [K,N]
// CTA tile 128x64, K-slab 16, 256 threads (8 warps -> 4x2 grid of 32x32 tiles).
// Requires: M%128==0, N%64==0, K%16==0, all pointers/lds 16B-aligned.
// EPI: 0 scale  1 +bias  2 conv+bn+relu  3 gaussian-W  4 newton (2*X - acc)
struct GemmP {
    const float* A; const float* B; float* C;
    int N, K, lda, ldb, ldc, zdiv;
    long sA1, sA2, sB1, sB2, sC1, sC2, sP0;
    float scale;
    const float* p0; const float* p1; const float* p2;
};

__device__ __forceinline__ float tf32hi(float x) {
    return __uint_as_float(__float_as_uint(x) & 0xFFFFE000u);
}
__device__ __forceinline__ void mma8(float* d, const unsigned* a, const unsigned* b) {
    asm volatile("mma.sync.aligned.m16n8k8.row.col.f32.tf32.tf32.f32 "
        "{%0,%1,%2,%3}, {%4,%5,%6,%7}, {%8,%9}, {%0,%1,%2,%3};"
        : "+f"(d[0]), "+f"(d[1]), "+f"(d[2]), "+f"(d[3])
        : "r"(a[0]), "r"(a[1]), "r"(a[2]), "r"(a[3]), "r"(b[0]), "r"(b[1]));
}
#define CPA16(dst, src) asm volatile("cp.async.ca.shared.global [%0], [%1], 16;" \
                                     :: "r"(dst), "l"(src))
#define CPCOMMIT()      asm volatile("cp.async.commit_group;")
#define CPWAIT0()       asm volatile("cp.async.wait_group 0;" ::: "memory")

template<int EPI, int BT>
__global__ void __launch_bounds__(256, 2) tgemm_k(GemmP p) {
    __shared__ float As[2][128*ASTR];
    __shared__ float Bs[2][1280];
    int z  = blockIdx.z;
    int zb = z / p.zdiv, zr = z % p.zdiv;
    const float* Ap = p.A + zb * p.sA1 + (long)zr * p.sA2;
    const float* Bp = p.B + zb * p.sB1 + (long)zr * p.sB2;
    float*       Cp = p.C + zb * p.sC1 + (long)zr * p.sC2;
    int bm = blockIdx.y * 128, bn = blockIdx.x * 64;
    int tid = threadIdx.x;
    int warp = tid >> 5, lane = tid & 31;
    int g = lane >> 2, t = lane & 3;
    int m0 = (warp >> 1) * 32, n0 = (warp & 1) * 32;

    // loader coords
    int lr0 = tid >> 2, ac4 = (tid & 3) * 4;        // A: 2 float4/thread (rows lr0, lr0+64)
    int bn_ = tid >> 2, bc4 = (tid & 3) * 4;        // B BT=1
    int bkr = tid >> 4, bnc = (tid & 15) * 4;       // B BT=0
    unsigned sA[2] = { (unsigned)__cvta_generic_to_shared(&As[0][0]),
                       (unsigned)__cvta_generic_to_shared(&As[1][0]) };
    unsigned sB[2] = { (unsigned)__cvta_generic_to_shared(&Bs[0][0]),
                       (unsigned)__cvta_generic_to_shared(&Bs[1][0]) };

    float acc[2][4][4];
#pragma unroll
    for (int i = 0; i < 2; i++)
#pragma unroll
        for (int j = 0; j < 4; j++)
#pragma unroll
            for (int r = 0; r < 4; r++) acc[i][j][r] = 0.f;

    int nSlab = p.K >> 4;

    auto issue = [&](int it) {
        int buf = it & 1;
        int k0 = it << 4;
        CPA16(sA[buf] + (unsigned)((lr0*ASTR + ac4) * 4),
              Ap + (long)(bm + lr0) * p.lda + k0 + ac4);
        CPA16(sA[buf] + (unsigned)(((lr0+64)*ASTR + ac4) * 4),
              Ap + (long)(bm + lr0 + 64) * p.lda + k0 + ac4);
        if (BT) CPA16(sB[buf] + (unsigned)((bn_*BSTR1 + bc4) * 4),
                      Bp + (long)(bn + bn_) * p.ldb + k0 + bc4);
        else    CPA16(sB[buf] + (unsigned)((bkr*BSTR0 + bnc) * 4),
                      Bp + (long)(k0 + bkr) * p.ldb + bn + bnc);
        CPCOMMIT();
    };

    issue(0);
    for (int it = 0; it < nSlab; it++) {
        CPWAIT0();
        __syncthreads();
        if (it + 1 < nSlab) issue(it + 1);
        const float* as = As[it & 1];
        const float* bs = Bs[it & 1];
#pragma unroll
        for (int ks = 0; ks < 2; ks++) {
            int kb = ks * 8;
            unsigned ah[2][4], al[2][4];
#pragma unroll
            for (int i = 0; i < 2; i++) {
                int mb = m0 + i*16;
                float r0 = as[(mb + g    )*ASTR + kb + t    ];
                float r1 = as[(mb + 8 + g)*ASTR + kb + t    ];
                float r2 = as[(mb + g    )*ASTR + kb + t + 4];
                float r3 = as[(mb + 8 + g)*ASTR + kb + t + 4];
                float h0 = tf32hi(r0), h1 = tf32hi(r1), h2 = tf32hi(r2), h3 = tf32hi(r3);
                ah[i][0] = __float_as_uint(h0); al[i][0] = __float_as_uint(r0 - h0);
                ah[i][1] = __float_as_uint(h1); al[i][1] = __float_as_uint(r1 - h1);
                ah[i][2] = __float_as_uint(h2); al[i][2] = __float_as_uint(r2 - h2);
                ah[i][3] = __float_as_uint(h3); al[i][3] = __float_as_uint(r3 - h3);
            }
            unsigned bh[4][2], bl[4][2];
#pragma unroll
            for (int j = 0; j < 4; j++) {
                int nb = n0 + j*8 + g;
                float r0, r1;
                if (BT) { r0 = bs[nb*BSTR1 + kb + t];   r1 = bs[nb*BSTR1 + kb + t + 4]; }
                else    { r0 = bs[(kb + t)*BSTR0 + nb]; r1 = bs[(kb + t + 4)*BSTR0 + nb]; }
                float h0 = tf32hi(r0), h1 = tf32hi(r1);
                bh[j][0] = __float_as_uint(h0); bl[j][0] = __float_as_uint(r0 - h0);
                bh[j][1] = __float_as_uint(h1); bl[j][1] = __float_as_uint(r1 - h1);
            }
#pragma unroll
            for (int i = 0; i < 2; i++)
#pragma unroll
                for (int j = 0; j < 4; j++) {
                    mma8(acc[i][j], ah[i], bh[j]);
                    mma8(acc[i][j], ah[i], bl[j]);
                    mma8(acc[i][j], al[i], bh[j]);
                }
        }
        __syncthreads();
    }

    const float* P0 = p.p0;
    if (EPI == 3 || EPI == 4) P0 = p.p0 + zb * p.sP0;
#pragma unroll
    for (int i = 0; i < 2; i++)
#pragma unroll
        for (int j = 0; j < 4; j++) {
            int m  = bm + m0 + i*16 + g;
            int n  = bn + n0 + j*8 + 2*t;
            float v0 = acc[i][j][0], v1 = acc[i][j][1];
            float v2 = acc[i][j][2], v3 = acc[i][j][3];
            if (EPI == 0) {
                v0 *= p.scale; v1 *= p.scale; v2 *= p.scale; v3 *= p.scale;
            } else if (EPI == 1) {
                v0 += p.p0[n]; v1 += p.p0[n+1]; v2 += p.p0[n]; v3 += p.p0[n+1];
            } else if (EPI == 2) {
                float g0 = 0.9999950000125f * p.p1[n],   b0 = p.p2[n];
                float g1 = 0.9999950000125f * p.p1[n+1], b1 = p.p2[n+1];
                v0 = fmaxf((v0 + p.p0[n])   * g0 + b0, 0.f);
                v1 = fmaxf((v1 + p.p0[n+1]) * g1 + b1, 0.f);
                v2 = fmaxf((v2 + p.p0[n])   * g0 + b0, 0.f);
                v3 = fmaxf((v3 + p.p0[n+1]) * g1 + b1, 0.f);
            } else if (EPI == 3) {
                float sm0 = P0[m], sm8 = P0[m+8], sn0 = P0[n], sn1 = P0[n+1];
                v0 = expf(-fmaxf(sm0 + sn0 - 2.f*v0, 0.f) * (1.f/1536.f));
                v1 = expf(-fmaxf(sm0 + sn1 - 2.f*v1, 0.f) * (1.f/1536.f));
                v2 = expf(-fmaxf(sm8 + sn0 - 2.f*v2, 0.f) * (1.f/1536.f));
                v3 = expf(-fmaxf(sm8 + sn1 - 2.f*v3, 0.f) * (1.f/1536.f));
            } else if (EPI == 4) {
                v0 = 2.f * P0[(long)m*p.ldc + n]       - v0;
                v1 = 2.f * P0[(long)m*p.ldc + n + 1]   - v1;
                v2 = 2.f * P0[(long)(m+8)*p.ldc + n]   - v2;
                v3 = 2.f * P0[(long)(m+8)*p.ldc + n+1] - v3;
            }
            Cp[(long)m*p.ldc + n]       = v0;
            Cp[(long)m*p.ldc + n + 1]   = v1;
            Cp[(long)(m+8)*p.ldc + n]   = v2;
            Cp[(long)(m+8)*p.ldc + n+1] = v3;
        }
}

// ---------------- elementwise / reduction kernels ----------------------------
__global__ void k_build_emb(const float* ge, const float* ue) {
    long i = (long)blockIdx.x * blockDim.x + threadIdx.x;
    if (i >= (long)BB*SN*DF) return;
    int d = i % DF; long bn = i / DF; int n = bn % SN; int b = (int)(bn / SN);
    float x = (n < SIDX) ? ge[((long)b*SIDX + n)*DF + d]
                         : ue[((long)b*SIDX + (n - SIDX))*DF + d];
    int half = d >> 1;
    float freq = expf((float)(2*half) * (-9.210340371976184f/768.f));
    float arg = (float)n * freq;
    float pe = (d & 1) ? cosf(arg) : sinf(arg);
    g_emb[i] = x + pe;
}

__global__ void k_softmax() {
    long row = blockIdx.x;
    float* r = g_s + row * SN;
    int tid = threadIdx.x;
    __shared__ float red[256];
    float v0 = r[tid], v1 = r[tid+256];
    red[tid] = fmaxf(v0, v1); __syncthreads();
    for (int s = 128; s > 0; s >>= 1) { if (tid < s) red[tid] = fmaxf(red[tid], red[tid+s]); __syncthreads(); }
    float m = red[0]; __syncthreads();
    float e0 = expf(v0 - m), e1 = expf(v1 - m);
    red[tid] = e0 + e1; __syncthreads();
    for (int s = 128; s > 0; s >>= 1) { if (tid < s) red[tid] += red[tid+s]; __syncthreads(); }
    float inv = 1.f / red[0];
    r[tid] = e0 * inv; r[tid+256] = e1 * inv;
}

__global__ void k_addln(const float* lng, const float* lnb) {
    int row = blockIdx.x;
    int b = row >> 8, rr = row & 255;
    float*       u  = g_emb + ((long)b*SN + SIDX + rr) * DF;
    const float* mh = g_mha + ((long)b*SIDX + rr) * DF;
    int tid = threadIdx.x;
    __shared__ float red[256];
    float x[3];
#pragma unroll
    for (int t = 0; t < 3; t++) x[t] = u[tid + t*256] + mh[tid + t*256];
    red[tid] = x[0] + x[1] + x[2]; __syncthreads();
    for (int s = 128; s > 0; s >>= 1) { if (tid < s) red[tid] += red[tid+s]; __syncthreads(); }
    float mean = red[0] * (1.f/768.f); __syncthreads();
    float vs = 0.f;
#pragma unroll
    for (int t = 0; t < 3; t++) { float d = x[t] - mean; vs += d*d; }
    red[tid] = vs; __syncthreads();
    for (int s = 128; s > 0; s >>= 1) { if (tid < s) red[tid] += red[tid+s]; __syncthreads(); }
    float inv = rsqrtf(red[0] * (1.f/768.f) + 1e-5f);
#pragma unroll
    for (int t = 0; t < 3; t++) {
        int d = tid + t*256;
        u[d] = (x[t] - mean) * inv * lng[d] + lnb[d];
    }
}

__global__ void k_wprep(const float* c1w, const float* c2w) {
    int i = blockIdx.x * blockDim.x + threadIdx.x;
    if (i < 128*768) {
        int c = i / 768, r = i % 768, k = r / 256, ci = r % 256;
        g_w1r[i] = c1w[(c*256 + ci)*3 + k];
    } else if (i < 128*768 + 128*384) {
        int j = i - 128*768;
        int c = j / 384, r = j % 384, k = r / 128, ci = r % 128;
        g_w2r[j] = c2w[(c*128 + ci)*3 + k];
    }
}

__global__ void k_im2col1() {
    long i = (long)blockIdx.x * blockDim.x + threadIdx.x;
    if (i >= (long)BB*SN*768) return;
    int d = i % 768; long bl = i / 768; int l = bl % SN; int b = (int)(bl / SN);
    int k = d / 256, ci = d % 256;
    int src = l + k - 1;
    g_x1[i] = (src >= 0 && src < SN) ? g_xp[((long)b*SN + src)*PJ + ci] : 0.f;
}

__global__ void k_im2col2() {
    long i = (long)blockIdx.x * blockDim.x + threadIdx.x;
    if (i >= (long)BB*SN*384) return;
    int d = i % 384; long bl = i / 384; int l = bl % SN; int b = (int)(bl / SN);
    int k = d / 128, ci = d % 128;
    int src = l + k - 1;
    g_x2[i] = (src >= 0 && src < SN) ? g_h1[((long)b*SN + src)*HID + ci] : 0.f;
}

__global__ void k_sigma_e(const float* ow, const float* ob) {
    int row = blockIdx.x;
    int tid = threadIdx.x;
    __shared__ float red[256];
    float part = (tid < HID) ? g_h2[(long)row*HID + tid] * ow[tid] : 0.f;
    red[tid] = part; __syncthreads();
    for (int s = 128; s > 0; s >>= 1) { if (tid < s) red[tid] += red[tid+s]; __syncthreads(); }
    float sig = red[0] + ob[0]; __syncthreads();
    float inv = 1.f / (sig + 1e-6f);
    const float* er = g_emb + (long)row*DF;
    float*       eo = g_e   + (long)row*DF;
    float ss = 0.f;
#pragma unroll
    for (int t = 0; t < 3; t++) {
        float e = er[tid + t*256] * inv;
        eo[tid + t*256] = e;
        ss += e*e;
    }
    red[tid] = ss; __syncthreads();
    for (int s = 128; s > 0; s >>= 1) { if (tid < s) red[tid] += red[tid+s]; __syncthreads(); }
    if (tid == 0) g_sq[row] = red[0];
}

__global__ void k_topk() {
    int row = blockIdx.x * (blockDim.x >> 5) + (threadIdx.x >> 5);
    int lane = threadIdx.x & 31;
    if (row >= BB*SN) return;
    const float* w = g_w + (long)row * SN;
    unsigned char* mk = g_mk + (long)row * SN;
    for (int j = lane; j < SN/4; j += 32) ((unsigned int*)mk)[j] = 0u;
    __syncwarp();
    float v[16];
#pragma unroll
    for (int j = 0; j < 16; j++) v[j] = w[lane + j*32];
    for (int t = 0; t < KTOP; t++) {
        float bm = -1.f; int bj = 0;
#pragma unroll
        for (int j = 0; j < 16; j++) {
            if (v[j] > bm) { bm = v[j]; bj = j; }
        }
        int bidx = lane + bj*32;
#pragma unroll
        for (int s = 16; s > 0; s >>= 1) {
            float om = __shfl_xor_sync(0xffffffffu, bm, s);
            int oi = __shfl_xor_sync(0xffffffffu, bidx, s);
            if (om > bm || (om == bm && oi < bidx)) { bm = om; bidx = oi; }
        }
        if ((bidx & 31) == lane) v[bidx >> 5] = -1.f;
        if (lane == 0) mk[bidx] = 1;
        __syncwarp();
    }
}

__global__ void k_degree() {
    int row = blockIdx.x;
    int b = row >> 9, n = row & 511;
    float* w = g_w + (long)row*SN;
    const unsigned char* mrow = g_mk + (long)row*SN;
    int tid = threadIdx.x;
    __shared__ float red[256];
    float s = 0.f;
    for (int m = tid; m < SN; m += 256) {
        int on = mrow[m] | g_mk[((long)(b*SN + m))*SN + n];
        float val = on ? w[m] : 0.f;
        w[m] = val;
        s += val;
    }
    red[tid] = s; __syncthreads();
    for (int st = 128; st > 0; st >>= 1) { if (tid < st) red[tid] += red[tid+st]; __syncthreads(); }
    if (tid == 0) g_dsi[row] = rsqrtf(red[0] + 1e-6f);
}

__global__ void k_buildA(const float* alpha) {
    long i = (long)blockIdx.x * blockDim.x + threadIdx.x;
    if (i >= (long)BB*SN*SN) return;
    int m = (int)(i % SN); long t = i / SN; int n = (int)(t % SN); int b = (int)(t / SN);
    float a = alpha[0];
    float s = g_dsi[b*SN+n] * g_w[i] * g_dsi[b*SN+m];
    float A = ((n==m) ? 1.f + 1e-6f : 0.f) - a * s;
    g_A[i] = A;
    g_Xa[i] = ((n==m) ? 2.f : 0.f) - A;
}

__global__ void k_scatter(const int* labels, const float* X, float* out) {
    int b = blockIdx.z;
    int m = blockIdx.y;
    int n = blockIdx.x * 128 + threadIdx.x;
    int lab = labels[b*SN + m];
    if (lab >= VOC) return;
    float v = X[((long)(b*SN + m))*SN + n];    // symmetric: prop[b,n,m]
    atomicAdd(out + ((long)(b*SN + n))*VOC + lab, v);
}

// ---------------- host side ---------------------------------------------------
static void run_tg(int epi, int bt, const GemmP& p, int M, int Z) {
    dim3 g(p.N / 64, M / 128, Z);
    dim3 b(256);
    if (epi == 0 && bt == 1) tgemm_k<0,1><<<g,b>>>(p);
    else if (epi == 0 && bt == 0) tgemm_k<0,0><<<g,b>>>(p);
    else if (epi == 1 && bt == 1) tgemm_k<1,1><<<g,b>>>(p);
    else if (epi == 2 && bt == 1) tgemm_k<2,1><<<g,b>>>(p);
    else if (epi == 3 && bt == 1) tgemm_k<3,1><<<g,b>>>(p);
    else if (epi == 4 && bt == 0) tgemm_k<4,0><<<g,b>>>(p);
}

extern "C" void kernel_launch(void* const* d_in, const int* in_sizes, int n_in,
                              void* d_out, int out_size) {
    const float* ge    = (const float*)d_in[0];
    const float* ue    = (const float*)d_in[1];
    const float* hs    = (const float*)d_in[2];
    const int*   lab   = (const int*)  d_in[3];
    const float* inw   = (const float*)d_in[4];
    const float* inb   = (const float*)d_in[5];
    const float* outw  = (const float*)d_in[6];
    const float* outb  = (const float*)d_in[7];
    const float* lng   = (const float*)d_in[8];
    const float* lnb   = (const float*)d_in[9];
    const float* pw    = (const float*)d_in[10];
    const float* pb    = (const float*)d_in[11];
    const float* c1w   = (const float*)d_in[12];
    const float* c1b   = (const float*)d_in[13];
    const float* bn1g  = (const float*)d_in[14];
    const float* bn1b  = (const float*)d_in[15];
    const float* c2w   = (const float*)d_in[16];
    const float* c2b   = (const float*)d_in[17];
    const float* bn2g  = (const float*)d_in[18];
    const float* bn2b  = (const float*)d_in[19];
    const float* ow    = (const float*)d_in[20];
    const float* ob    = (const float*)d_in[21];
    const float* alpha = (const float*)d_in[22];
    float* out = (float*)d_out;

    void* vp;
    cudaGetSymbolAddress(&vp, g_emb); float* p_emb = (float*)vp;
    cudaGetSymbolAddress(&vp, g_q);   float* p_q   = (float*)vp;
    cudaGetSymbolAddress(&vp, g_kb);  float* p_kb  = (float*)vp;
    cudaGetSymbolAddress(&vp, g_vb);  float* p_vb  = (float*)vp;
    cudaGetSymbolAddress(&vp, g_s);   float* p_s   = (float*)vp;
    cudaGetSymbolAddress(&vp, g_o);   float* p_o   = (float*)vp;
    cudaGetSymbolAddress(&vp, g_mha); float* p_mha = (float*)vp;
    cudaGetSymbolAddress(&vp, g_xp);  float* p_xp  = (float*)vp;
    cudaGetSymbolAddress(&vp, g_x1);  float* p_x1  = (float*)vp;
    cudaGetSymbolAddress(&vp, g_h1);  float* p_h1  = (float*)vp;
    cudaGetSymbolAddress(&vp, g_x2);  float* p_x2  = (float*)vp;
    cudaGetSymbolAddress(&vp, g_h2);  float* p_h2  = (float*)vp;
    cudaGetSymbolAddress(&vp, g_e);   float* p_e   = (float*)vp;
    cudaGetSymbolAddress(&vp, g_sq);  float* p_sq  = (float*)vp;
    cudaGetSymbolAddress(&vp, g_w);   float* p_w   = (float*)vp;
    cudaGetSymbolAddress(&vp, g_A);   float* p_A   = (float*)vp;
    cudaGetSymbolAddress(&vp, g_Xa);  float* p_Xa  = (float*)vp;
    cudaGetSymbolAddress(&vp, g_Xb);  float* p_Xb  = (float*)vp;
    cudaGetSymbolAddress(&vp, g_T);   float* p_T   = (float*)vp;
    cudaGetSymbolAddress(&vp, g_w1r); float* p_w1r = (float*)vp;
    cudaGetSymbolAddress(&vp, g_w2r); float* p_w2r = (float*)vp;

    // 1. emb = concat + PE ; weight reshapes
    k_build_emb<<<(BB*SN*DF + 255)/256, 256>>>(ge, ue);
    k_wprep<<<(128*768 + 128*384)/256, 256>>>(c1w, c2w);

    GemmP p;
    p.zdiv = 1; p.scale = 1.f;
    p.sA1 = p.sA2 = p.sB1 = p.sB2 = p.sC1 = p.sC2 = p.sP0 = 0;
    p.p0 = p.p1 = p.p2 = 0;

    // 2. Q = u @ wq^T + bq   (batched over b, M=256 per batch)
    p.A = p_emb + SIDX*DF; p.sA1 = (long)SN*DF; p.lda = DF;
    p.B = inw;             p.ldb = DF;  p.sB1 = 0;
    p.C = p_q;  p.sC1 = (long)SIDX*DF; p.ldc = DF;
    p.N = DF; p.K = DF; p.p0 = inb;
    run_tg(1, 1, p, SIDX, BB);
    // 3. K, V = hs @ w^T + b (M=4096)
    p.A = hs; p.sA1 = 0; p.lda = DF;
    p.B = inw + DF*DF;  p.C = p_kb; p.sC1 = 0; p.p0 = inb + DF;
    run_tg(1, 1, p, BB*SN, 1);
    p.B = inw + 2*DF*DF; p.C = p_vb; p.p0 = inb + 2*DF;
    run_tg(1, 1, p, BB*SN, 1);

    // 4. scores = Q K^T / 8  (z = b*h, K=64)
    p.zdiv = NH;
    p.A = p_q;  p.sA1 = (long)SIDX*DF; p.sA2 = HD; p.lda = DF;
    p.B = p_kb; p.sB1 = (long)SN*DF;   p.sB2 = HD; p.ldb = DF;
    p.C = p_s;  p.sC1 = (long)NH*SIDX*SN; p.sC2 = (long)SIDX*SN; p.ldc = SN;
    p.N = SN; p.K = HD; p.scale = 0.125f;
    run_tg(0, 1, p, SIDX, BB*NH);
    // 5. softmax
    k_softmax<<<BB*NH*SIDX, 256>>>();
    // 6. o = attn @ V  (BT=0, N=64)
    p.A = p_s;  p.sA1 = (long)NH*SIDX*SN; p.sA2 = (long)SIDX*SN; p.lda = SN;
    p.B = p_vb; p.sB1 = (long)SN*DF; p.sB2 = HD; p.ldb = DF;
    p.C = p_o;  p.sC1 = (long)SIDX*DF; p.sC2 = HD; p.ldc = DF;
    p.N = HD; p.K = SN; p.scale = 1.f;
    run_tg(0, 0, p, SIDX, BB*NH);
    // 7. mha = o @ out_w^T + out_b  (M=2048)
    p.zdiv = 1; p.sA1 = p.sA2 = p.sB1 = p.sB2 = p.sC1 = p.sC2 = 0;
    p.A = p_o; p.lda = DF; p.B = outw; p.ldb = DF;
    p.C = p_mha; p.ldc = DF; p.N = DF; p.K = DF; p.p0 = outb;
    run_tg(1, 1, p, BB*SIDX, 1);
    // 8. u = LN(u + mha)
    k_addln<<<BB*SIDX, 256>>>(lng, lnb);
    // 9. xp = emb @ proj_w^T + proj_b  (M=4096, N=256)
    p.A = p_emb; p.lda = DF; p.B = pw; p.ldb = DF;
    p.C = p_xp; p.ldc = PJ; p.N = PJ; p.K = DF; p.p0 = pb;
    run_tg(1, 1, p, BB*SN, 1);
    // 10. conv1 + bn + relu  (M=4096, N=128, K=768)
    k_im2col1<<<(BB*SN*768 + 255)/256, 256>>>();
    p.A = p_x1; p.lda = 768; p.B = p_w1r; p.ldb = 768;
    p.C = p_h1; p.ldc = HID; p.N = HID; p.K = 768;
    p.p0 = c1b; p.p1 = bn1g; p.p2 = bn1b;
    run_tg(2, 1, p, BB*SN, 1);
    // 11. conv2 + bn + relu  (M=4096, N=128, K=384)
    k_im2col2<<<(BB*SN*384 + 255)/256, 256>>>();
    p.A = p_x2; p.lda = 384; p.B = p_w2r; p.ldb = 384;
    p.C = p_h2; p.ldc = HID; p.N = HID; p.K = 384;
    p.p0 = c2b; p.p1 = bn2g; p.p2 = bn2b;
    run_tg(2, 1, p, BB*SN, 1);
    // 12. sigma, e, sq
    k_sigma_e<<<BB*SN, 256>>>(ow, ob);
    // 13. W = exp(-(d2/768)/2)  (M=512, N=512, K=768, z=b)
    p.A = p_e; p.sA1 = (long)SN*DF; p.lda = DF;
    p.B = p_e; p.sB1 = (long)SN*DF; p.ldb = DF;
    p.C = p_w; p.sC1 = (long)SN*SN; p.ldc = SN;
    p.N = SN; p.K = DF; p.p0 = p_sq; p.sP0 = SN;
    run_tg(3, 1, p, SN, BB);
    // 14. top-k mask, symmetrize+degree, build A and X1=2I-A
    k_topk<<<BB*SN/4, 128>>>();
    k_degree<<<BB*SN, 256>>>();
    k_buildA<<<(BB*SN*SN + 255)/256, 256>>>(alpha);
    // 15. Newton-Schulz: X <- 2X - X(AX), 9 iters (X1 = 2I - A already)
    float* Xc = p_Xa; float* Xn = p_Xb;
    for (int it = 0; it < 9; it++) {
        // T = A @ Xc
        p.A = p_A;  p.sA1 = (long)SN*SN; p.sA2 = 0; p.lda = SN;
        p.B = Xc;   p.sB1 = (long)SN*SN; p.sB2 = 0; p.ldb = SN;
        p.C = p_T;  p.sC1 = (long)SN*SN; p.ldc = SN;
        p.N = SN; p.K = SN; p.scale = 1.f; p.p0 = 0; p.sP0 = 0;
        run_tg(0, 0, p, SN, BB);
        // Xn = 2*Xc - Xc @ T
        p.A = Xc; p.B = p_T; p.C = Xn;
        p.p0 = Xc; p.sP0 = (long)SN*SN;
        run_tg(4, 0, p, SN, BB);
        float* t = Xc; Xc = Xn; Xn = t;
    }
    // 16. out = prop @ one_hot(labels): zero + scatter (prop symmetric)
    cudaMemsetAsync(out, 0, (size_t)out_size * sizeof(float));
    dim3 sg(SN/128, SN, BB);
    k_scatter<<<sg, 128>>>(lab, Xc, out);
}